// round 6
// baseline (speedup 1.0000x reference)
#include <cuda_runtime.h>
#include <cuda_fp16.h>

#define NFLAT 1056768   /* 32*256*129 */
#define PLANE_F 33024   /* 256*129 */
#define PIX 2097152     /* 32*256*256 per (b,c) plane */
#define NREAL 25165824  /* 12 * PIX */
#define PBLK 2048       /* pack blocks per plane = PIX/1024 */

__device__ float   d_G[3*5*9*9*2];   // [c][k2][g0][g1][re/im] (static zero-init)
__device__ __half2 d_pairs[NREAL];   // staggered x-pairs: (v[x], v[x+1 clamped])

__device__ __forceinline__ unsigned pk2(float a, float b) {
    __half2 h = __floats2half2_rn(a, b);
    return *reinterpret_cast<unsigned*>(&h);
}

// ---------------- build: dense spectral box from sparse feed ----------------
__device__ void build_body(const float* __restrict__ seeds,
                           const float* __restrict__ Pk,
                           const float* __restrict__ defscale,
                           const int*  __restrict__ feed_idx, int fdim) {
    // d_G zero at load; every call rewrites the same slots with the same
    // values (feed_idx constant) -> deterministic.
    const float inv_n = 1.0f / 2097152.0f;          // irfftn normalization
    for (int j = threadIdx.x; j < fdim; j += 256) {
        int flat = feed_idx[j];
        int part = flat / NFLAT;                    // 0 = re, 1 = im
        int r = flat - part * NFLAT;
        int k0 = r / PLANE_F; r -= k0 * PLANE_F;
        int k1 = r / 129;
        int k2 = r - k1 * 129;
        int f0 = (k0 <= 16) ? k0 : k0 - 32;         // |f0| <= 4 (ksq<=16)
        int f1 = (k1 <= 128) ? k1 : k1 - 256;
        float w = (k0 == 0 && k1 == 0 && k2 == 0) ? 1.0f : 2.0f;
        float base = Pk[j] * w * inv_n;
        int slot = ((k2 * 9 + (f0 + 4)) * 9 + (f1 + 4)) * 2 + part;
        for (int c = 0; c < 3; c++) {
            float a = seeds[c * fdim + j] * defscale[c] * base;
            d_G[c * (5*9*9*2) + slot] = a;          // unique slot: plain store
        }
    }
}

// ---------------- pack: one 1024-float chunk of one plane -------------------
__device__ void pack_body(const float* __restrict__ fr, int chunk) {
    int i = (chunk * 256 + threadIdx.x) * 4;        // i % 256 in {0,4,...,252}
    float4 f = __ldcs(reinterpret_cast<const float4*>(fr + i));
    float s = __ldcs(fr + min(i + 4, NREAL - 1));
    int pos = i & 255;
    float n3 = (pos == 252) ? f.w : s;              // clamp pair at row end
    uint4 u;
    u.x = pk2(f.x, f.y);
    u.y = pk2(f.y, f.z);
    u.z = pk2(f.z, f.w);
    u.w = pk2(f.w, n3);
    *reinterpret_cast<uint4*>(reinterpret_cast<unsigned*>(d_pairs) + i) = u;
}

// ---------------- deform: planes [LO, LO+CNT) for one (i0,i1) row -----------
template<int LO, int CNT>
__device__ void deform_body(float* __restrict__ out, int bid) {
    __shared__ float2 sW[256];
    __shared__ float2 sP[135];
    __shared__ float2 sH[15];
    int tid = threadIdx.x;
    int i1 = bid & 255;
    int i0 = bid >> 8;
    {   // twiddle table via MUFU
        float sv, cv;
        sincospif((float)tid / 128.0f, &sv, &cv);
        sW[tid] = make_float2(cv, sv);
    }
    __syncthreads();

    // Fold (k0,k1): 135 threads each sum 9 k1-terms
    if (tid < 135) {
        int c   = tid / 45;
        int rem = tid - c * 45;
        int k2  = rem / 9;
        int g0  = rem - k2 * 9;
        int f0  = g0 - 4;
        int t0  = (8 * f0 * i0 + 4096) & 255;
        float2 acc = make_float2(0.f, 0.f);
        const float* Gp = d_G + ((c * 5 + k2) * 9 + g0) * 9 * 2;
        #pragma unroll
        for (int g1 = 0; g1 < 9; g1++) {
            int f1 = g1 - 4;
            int tt = (t0 + f1 * i1 + 4096) & 255;
            float gr = Gp[g1 * 2 + 0], gi = Gp[g1 * 2 + 1];
            float2 wv = sW[tt];
            acc.x += gr * wv.x - gi * wv.y;
            acc.y += gr * wv.y + gi * wv.x;
        }
        sP[tid] = acc;
    }
    __syncthreads();
    if (tid < 15) {
        int c = tid / 5, k2 = tid - c * 5;
        float2 h = make_float2(0.f, 0.f);
        int base = c * 45 + k2 * 9;
        #pragma unroll
        for (int g0 = 0; g0 < 9; g0++) { h.x += sP[base + g0].x; h.y += sP[base + g0].y; }
        sH[tid] = h;
    }
    __syncthreads();

    // disp_c = Re( sum_k2 H[c][k2] * W[k2*i2] )
    int i2 = tid;
    float dd[3];
    #pragma unroll
    for (int c = 0; c < 3; c++) {
        float acc = 0.f;
        #pragma unroll
        for (int k2 = 0; k2 < 5; k2++) {
            int tt = (k2 * i2) & 255;
            float2 h = sH[c * 5 + k2];
            float2 wv = sW[tt];
            acc += h.x * wv.x - h.y * wv.y;
        }
        dd[c] = acc;
    }

    // grid_sample: bilinear, border clamp, align_corners=True at i - disp
    float fz = fminf(fmaxf((float)i0 - dd[0], 0.f), 31.f);
    float fy = fminf(fmaxf((float)i1 - dd[1], 0.f), 255.f);
    float fx = fminf(fmaxf((float)i2 - dd[2], 0.f), 255.f);
    int z0 = (int)fz, y0 = (int)fy, x0 = (int)fx;
    float wz = fz - (float)z0, wy = fy - (float)y0, wx = fx - (float)x0;
    int z1 = min(z0 + 1, 31), y1 = min(y0 + 1, 255);

    int q00 = z0 * 65536 + y0 * 256 + x0;
    int q01 = z0 * 65536 + y1 * 256 + x0;
    int q10 = z1 * 65536 + y0 * 256 + x0;
    int q11 = z1 * 65536 + y1 * 256 + x0;
    int pix = i0 * 65536 + i1 * 256 + i2;

    float iwx = 1.f - wx, iwy = 1.f - wy, iwz = 1.f - wz;

    #pragma unroll
    for (int g = 0; g < CNT; g += 4) {
        constexpr int GMAX = 4;
        __half2 v[GMAX * 4];
        int e = (g + 4 < CNT) ? g + 4 : CNT;
        #pragma unroll
        for (int b = 0; b < GMAX; b++) {
            if (g + b < CNT) {
                const __half2* p = d_pairs + (size_t)(LO + g + b) * PIX;
                v[b*4+0] = __ldg(p + q00);
                v[b*4+1] = __ldg(p + q01);
                v[b*4+2] = __ldg(p + q10);
                v[b*4+3] = __ldg(p + q11);
            }
        }
        #pragma unroll
        for (int b = 0; b < GMAX; b++) {
            if (g + b < CNT) {
                float2 v00 = __half22float2(v[b*4+0]);
                float2 v01 = __half22float2(v[b*4+1]);
                float2 v10 = __half22float2(v[b*4+2]);
                float2 v11 = __half22float2(v[b*4+3]);
                float c00 = v00.x * iwx + v00.y * wx;
                float c01 = v01.x * iwx + v01.y * wx;
                float c10 = v10.x * iwx + v10.y * wx;
                float c11 = v11.x * iwx + v11.y * wx;
                float c0 = c00 * iwy + c01 * wy;
                float c1 = c10 * iwy + c11 * wy;
                __stcs(out + (size_t)(LO + g + b) * PIX + pix, c0 * iwz + c1 * wz);
            }
        }
        (void)e;
    }
}

// ---------------- launches ----------------
// K1: build + pack planes 0..2
__global__ void __launch_bounds__(256) k1_kernel(
        const float* __restrict__ fr,
        const float* __restrict__ seeds,
        const float* __restrict__ Pk,
        const float* __restrict__ defscale,
        const int*  __restrict__ feed_idx, int fdim) {
    if (blockIdx.x == 0) build_body(seeds, Pk, defscale, feed_idx, fdim);
    else                 pack_body(fr, blockIdx.x - 1);      // chunks 0 .. 3*PBLK-1
}

// K2: pack planes 3..11 (first in grid order) || deform planes 0..2
__global__ void __launch_bounds__(256) k2_kernel(const float* __restrict__ fr,
                                                 float* __restrict__ out) {
    if (blockIdx.x < 9 * PBLK) pack_body(fr, 3 * PBLK + blockIdx.x);
    else                       deform_body<0, 3>(out, blockIdx.x - 9 * PBLK);
}

// K3: deform planes 3..11
__global__ void __launch_bounds__(256) k3_kernel(float* __restrict__ out) {
    deform_body<3, 9>(out, blockIdx.x);
}

extern "C" void kernel_launch(void* const* d_in, const int* in_sizes, int n_in,
                              void* d_out, int out_size) {
    const float* fr       = (const float*)d_in[0];
    const float* seeds    = (const float*)d_in[1];
    const float* Pk       = (const float*)d_in[2];
    const float* defscale = (const float*)d_in[3];
    const int*   feed_idx = (const int*)d_in[5];
    int fdim = in_sizes[5];
    float* out = (float*)d_out;

    k1_kernel<<<1 + 3 * PBLK, 256>>>(fr, seeds, Pk, defscale, feed_idx, fdim);
    k2_kernel<<<9 * PBLK + 8192, 256>>>(fr, out);
    k3_kernel<<<8192, 256>>>(out);
}

// round 7
// speedup vs baseline: 1.0913x; 1.0913x over previous
#include <cuda_runtime.h>
#include <cuda_fp16.h>

#define NFLAT 1056768   /* 32*256*129 */
#define PLANE_F 33024   /* 256*129 */
#define PIX 2097152     /* 32*256*256 per (b,c) plane */
#define NREAL 25165824  /* 12 * PIX */
#define PACK_BLOCKS 24576  /* NREAL/4/256 */

__device__ float   d_G[3*5*9*9*2];   // [c][k2][g0][g1][re/im] (static zero-init)
__device__ __half2 d_pairs[NREAL];   // staggered x-pairs: (v[x], v[x+1 clamped])

__device__ __forceinline__ unsigned pk2(float a, float b) {
    __half2 h = __floats2half2_rn(a, b);
    return *reinterpret_cast<unsigned*>(&h);
}

// Fused: blocks [0, PACK_BLOCKS) pack fr into staggered half2 pairs;
// block PACK_BLOCKS builds the dense spectral box d_G.
__global__ void __launch_bounds__(256) pack_build_kernel(
        const float* __restrict__ fr,
        const float* __restrict__ seeds,
        const float* __restrict__ Pk,
        const float* __restrict__ defscale,
        const int*  __restrict__ feed_idx,
        int fdim) {
    if (blockIdx.x < PACK_BLOCKS) {
        int i = (blockIdx.x * 256 + threadIdx.x) * 4;   // i % 256 in {0,4,...,252}
        float4 f = __ldcs(reinterpret_cast<const float4*>(fr + i));
        float s = __ldcs(fr + min(i + 4, NREAL - 1));
        int pos = i & 255;
        float n3 = (pos == 252) ? f.w : s;              // clamp pair at row end
        uint4 u;
        u.x = pk2(f.x, f.y);
        u.y = pk2(f.y, f.z);
        u.z = pk2(f.z, f.w);
        u.w = pk2(f.w, n3);
        *reinterpret_cast<uint4*>(reinterpret_cast<unsigned*>(d_pairs) + i) = u;
    } else {
        // d_G zero at load; every call rewrites the same slots with the same
        // values (feed_idx constant) -> deterministic.
        const float inv_n = 1.0f / 2097152.0f;          // irfftn normalization
        for (int j = threadIdx.x; j < fdim; j += 256) {
            int flat = feed_idx[j];
            int part = flat / NFLAT;                    // 0 = re, 1 = im
            int r = flat - part * NFLAT;
            int k0 = r / PLANE_F; r -= k0 * PLANE_F;
            int k1 = r / 129;
            int k2 = r - k1 * 129;
            int f0 = (k0 <= 16) ? k0 : k0 - 32;         // |f0| <= 4 (ksq<=16)
            int f1 = (k1 <= 128) ? k1 : k1 - 256;
            float w = (k0 == 0 && k1 == 0 && k2 == 0) ? 1.0f : 2.0f;
            float base = Pk[j] * w * inv_n;
            int slot = ((k2 * 9 + (f0 + 4)) * 9 + (f1 + 4)) * 2 + part;
            for (int c = 0; c < 3; c++) {
                float a = seeds[c * fdim + j] * defscale[c] * base;
                d_G[c * (5*9*9*2) + slot] = a;          // unique slot: plain store
            }
        }
    }
}

// One block = 8 consecutive i1 rows of one i0 slab. Plane-pair outer loop,
// row inner loop -> tap lines fetched once per plane-pair, L1-hit for the
// remaining 7 rows.
__global__ void __launch_bounds__(256) deform_kernel(float* __restrict__ out) {
    __shared__ float2 sW[256];
    __shared__ float2 sH[120];                     // [r][c][k2]
    __shared__ __align__(16) char sBuf[32768];     // union: G (9.7KB) then taps (32KB)
    float2* sG = reinterpret_cast<float2*>(sBuf);  // 1215 float2
    float4* sT = reinterpret_cast<float4*>(sBuf);  // 2048 float4

    int tid = threadIdx.x;
    int i1base = blockIdx.x * 8;
    int i0 = blockIdx.y;

    {   // twiddle table via MUFU
        float sv, cv;
        sincospif((float)tid / 128.0f, &sv, &cv);
        sW[tid] = make_float2(cv, sv);
    }
    // stage G into smem (2430 floats)
    {
        const float2* Gg = reinterpret_cast<const float2*>(d_G);
        for (int j = tid; j < 1215; j += 256) sG[j] = Gg[j];
    }
    __syncthreads();

    // Fold: H[r][c][k2] = sum_{g0,g1} G * W[(8*f0*i0 + f1*i1) & 255]
    if (tid < 120) {
        int r = tid / 15, rem = tid - r * 15;
        int c = rem / 5, k2 = rem - c * 5;
        int i1 = i1base + r;
        const float2* Gc = sG + (c * 5 + k2) * 81;
        float2 acc = make_float2(0.f, 0.f);
        #pragma unroll
        for (int g0 = 0; g0 < 9; g0++) {
            int t0 = 8 * (g0 - 4) * i0 + 8192;
            #pragma unroll
            for (int g1 = 0; g1 < 9; g1++) {
                int tt = (t0 + (g1 - 4) * i1) & 255;
                float2 gv = Gc[g0 * 9 + g1];
                float2 wv = sW[tt];
                acc.x += gv.x * wv.x - gv.y * wv.y;
                acc.y += gv.x * wv.y + gv.y * wv.x;
            }
        }
        sH[tid] = acc;
    }
    __syncthreads();

    // Per-row taps: disp -> (x0,y0,z0) + (wx,wy,wz), stored in sT (overwrites sG)
    int i2 = tid;
    #pragma unroll
    for (int r = 0; r < 8; r++) {
        float dd[3];
        #pragma unroll
        for (int c = 0; c < 3; c++) {
            float acc = 0.f;
            #pragma unroll
            for (int k2 = 0; k2 < 5; k2++) {
                float2 h = sH[r * 15 + c * 5 + k2];
                float2 wv = sW[(k2 * i2) & 255];
                acc += h.x * wv.x - h.y * wv.y;
            }
            dd[c] = acc;
        }
        int i1 = i1base + r;
        float fz = fminf(fmaxf((float)i0 - dd[0], 0.f), 31.f);
        float fy = fminf(fmaxf((float)i1 - dd[1], 0.f), 255.f);
        float fx = fminf(fmaxf((float)i2 - dd[2], 0.f), 255.f);
        int z0 = (int)fz, y0 = (int)fy, x0 = (int)fx;
        float4 tp;
        tp.x = __int_as_float(x0 | (y0 << 8) | (z0 << 16));
        tp.y = fx - (float)x0;
        tp.z = fy - (float)y0;
        tp.w = fz - (float)z0;
        sT[r * 256 + tid] = tp;
    }
    __syncthreads();

    // Gather: plane-pairs outer (L1 locality), rows inner
    int pixbase = i0 * 65536 + i1base * 256 + tid;
    #pragma unroll
    for (int g = 0; g < 6; g++) {
        const __half2* p0 = d_pairs + (size_t)(2 * g) * PIX;
        const __half2* p1 = p0 + PIX;
        #pragma unroll
        for (int r = 0; r < 8; r++) {
            float4 tp = sT[r * 256 + tid];
            int m = __float_as_int(tp.x);
            int x0 = m & 255, y0 = (m >> 8) & 255, z0 = (m >> 16) & 255;
            int y1 = min(y0 + 1, 255), z1 = min(z0 + 1, 31);
            int q00 = z0 * 65536 + y0 * 256 + x0;
            int q01 = z0 * 65536 + y1 * 256 + x0;
            int q10 = z1 * 65536 + y0 * 256 + x0;
            int q11 = z1 * 65536 + y1 * 256 + x0;
            float wx = tp.y, wy = tp.z, wz = tp.w;
            float iwx = 1.f - wx, iwy = 1.f - wy, iwz = 1.f - wz;

            __half2 a00 = __ldg(p0 + q00), a01 = __ldg(p0 + q01);
            __half2 a10 = __ldg(p0 + q10), a11 = __ldg(p0 + q11);
            __half2 b00 = __ldg(p1 + q00), b01 = __ldg(p1 + q01);
            __half2 b10 = __ldg(p1 + q10), b11 = __ldg(p1 + q11);

            float2 v00 = __half22float2(a00), v01 = __half22float2(a01);
            float2 v10 = __half22float2(a10), v11 = __half22float2(a11);
            float c00 = v00.x * iwx + v00.y * wx;
            float c01 = v01.x * iwx + v01.y * wx;
            float c10 = v10.x * iwx + v10.y * wx;
            float c11 = v11.x * iwx + v11.y * wx;
            float r0 = (c00 * iwy + c01 * wy) * iwz + (c10 * iwy + c11 * wy) * wz;

            v00 = __half22float2(b00); v01 = __half22float2(b01);
            v10 = __half22float2(b10); v11 = __half22float2(b11);
            c00 = v00.x * iwx + v00.y * wx;
            c01 = v01.x * iwx + v01.y * wx;
            c10 = v10.x * iwx + v10.y * wx;
            c11 = v11.x * iwx + v11.y * wx;
            float r1 = (c00 * iwy + c01 * wy) * iwz + (c10 * iwy + c11 * wy) * wz;

            int pix = pixbase + r * 256;
            __stcs(out + (size_t)(2 * g) * PIX + pix, r0);
            __stcs(out + (size_t)(2 * g + 1) * PIX + pix, r1);
        }
    }
}

extern "C" void kernel_launch(void* const* d_in, const int* in_sizes, int n_in,
                              void* d_out, int out_size) {
    const float* fr       = (const float*)d_in[0];
    const float* seeds    = (const float*)d_in[1];
    const float* Pk       = (const float*)d_in[2];
    const float* defscale = (const float*)d_in[3];
    const int*   feed_idx = (const int*)d_in[5];
    int fdim = in_sizes[5];

    pack_build_kernel<<<PACK_BLOCKS + 1, 256>>>(fr, seeds, Pk, defscale, feed_idx, fdim);
    dim3 g(32, 32);
    deform_kernel<<<g, 256>>>((float*)d_out);
}

// round 8
// speedup vs baseline: 1.2434x; 1.1395x over previous
#include <cuda_runtime.h>
#include <cuda_fp16.h>

#define NFLAT 1056768   /* 32*256*129 */
#define PLANE_F 33024   /* 256*129 */
#define PIX 2097152     /* 32*256*256 per (b,c) plane */
#define NREAL 25165824  /* 12 * PIX */
#define PACK_BLOCKS 24576  /* NREAL/4/256 */

__device__ float   d_G[3*5*9*9*2];   // [c][k2][g0][g1][re/im] (static zero-init)
__device__ __half2 d_pairs[NREAL];   // staggered x-pairs: (v[x], v[x+1 clamped])

__device__ __forceinline__ unsigned pk2(float a, float b) {
    __half2 h = __floats2half2_rn(a, b);
    return *reinterpret_cast<unsigned*>(&h);
}

// Fused: blocks [0, PACK_BLOCKS) pack fr into staggered half2 pairs;
// block PACK_BLOCKS builds the dense spectral box d_G.
__global__ void __launch_bounds__(256) pack_build_kernel(
        const float* __restrict__ fr,
        const float* __restrict__ seeds,
        const float* __restrict__ Pk,
        const float* __restrict__ defscale,
        const int*  __restrict__ feed_idx,
        int fdim) {
    if (blockIdx.x < PACK_BLOCKS) {
        int i = (blockIdx.x * 256 + threadIdx.x) * 4;   // i % 256 in {0,4,...,252}
        float4 f = __ldcs(reinterpret_cast<const float4*>(fr + i));
        float s = __ldcs(fr + min(i + 4, NREAL - 1));
        int pos = i & 255;
        float n3 = (pos == 252) ? f.w : s;              // clamp pair at row end
        uint4 u;
        u.x = pk2(f.x, f.y);
        u.y = pk2(f.y, f.z);
        u.z = pk2(f.z, f.w);
        u.w = pk2(f.w, n3);
        *reinterpret_cast<uint4*>(reinterpret_cast<unsigned*>(d_pairs) + i) = u;
    } else {
        // d_G zero at load; every call rewrites the same slots with the same
        // values (feed_idx constant) -> deterministic.
        const float inv_n = 1.0f / 2097152.0f;          // irfftn normalization
        for (int j = threadIdx.x; j < fdim; j += 256) {
            int flat = feed_idx[j];
            int part = flat / NFLAT;                    // 0 = re, 1 = im
            int r = flat - part * NFLAT;
            int k0 = r / PLANE_F; r -= k0 * PLANE_F;
            int k1 = r / 129;
            int k2 = r - k1 * 129;
            int f0 = (k0 <= 16) ? k0 : k0 - 32;         // |f0| <= 4 (ksq<=16)
            int f1 = (k1 <= 128) ? k1 : k1 - 256;
            float w = (k0 == 0 && k1 == 0 && k2 == 0) ? 1.0f : 2.0f;
            float base = Pk[j] * w * inv_n;
            int slot = ((k2 * 9 + (f0 + 4)) * 9 + (f1 + 4)) * 2 + part;
            for (int c = 0; c < 3; c++) {
                float a = seeds[c * fdim + j] * defscale[c] * base;
                d_G[c * (5*9*9*2) + slot] = a;          // unique slot: plain store
            }
        }
    }
}

__global__ void __launch_bounds__(256) deform_kernel(float* __restrict__ out) {
    __shared__ float2 sW[256];
    __shared__ float2 sP[135];
    __shared__ float2 sH[15];
    int tid = threadIdx.x;
    int i1 = blockIdx.x;
    int i0 = blockIdx.y;
    {   // twiddle table via MUFU, no global round-trip
        float sv, cv;
        sincospif((float)tid / 128.0f, &sv, &cv);
        sW[tid] = make_float2(cv, sv);
    }
    __syncthreads();

    // Fold (k0,k1) for this (i0,i1) row: 135 threads each sum 9 k1-terms
    if (tid < 135) {
        int c   = tid / 45;
        int rem = tid - c * 45;
        int k2  = rem / 9;
        int g0  = rem - k2 * 9;
        int f0  = g0 - 4;
        int t0  = (8 * f0 * i0 + 4096) & 255;
        float2 acc = make_float2(0.f, 0.f);
        const float* Gp = d_G + ((c * 5 + k2) * 9 + g0) * 9 * 2;
        #pragma unroll
        for (int g1 = 0; g1 < 9; g1++) {
            int f1 = g1 - 4;
            int tt = (t0 + f1 * i1 + 4096) & 255;
            float gr = Gp[g1 * 2 + 0], gi = Gp[g1 * 2 + 1];
            float2 wv = sW[tt];
            acc.x += gr * wv.x - gi * wv.y;
            acc.y += gr * wv.y + gi * wv.x;
        }
        sP[tid] = acc;
    }
    __syncthreads();
    if (tid < 15) {
        int c = tid / 5, k2 = tid - c * 5;
        float2 h = make_float2(0.f, 0.f);
        int base = c * 45 + k2 * 9;
        #pragma unroll
        for (int g0 = 0; g0 < 9; g0++) { h.x += sP[base + g0].x; h.y += sP[base + g0].y; }
        sH[tid] = h;
    }
    __syncthreads();

    // Per-thread displacement: disp_c = Re( sum_k2 H[c][k2] * W[k2*i2] )
    int i2 = tid;
    float dd[3];
    #pragma unroll
    for (int c = 0; c < 3; c++) {
        float acc = 0.f;
        #pragma unroll
        for (int k2 = 0; k2 < 5; k2++) {
            int tt = (k2 * i2) & 255;
            float2 h = sH[c * 5 + k2];
            float2 wv = sW[tt];
            acc += h.x * wv.x - h.y * wv.y;
        }
        dd[c] = acc;
    }

    // grid_sample: bilinear, border clamp, align_corners=True -> sample at i - disp
    float fz = fminf(fmaxf((float)i0 - dd[0], 0.f), 31.f);
    float fy = fminf(fmaxf((float)i1 - dd[1], 0.f), 255.f);
    float fx = fminf(fmaxf((float)i2 - dd[2], 0.f), 255.f);
    int z0 = (int)fz, y0 = (int)fy, x0 = (int)fx;
    float wz = fz - (float)z0, wy = fy - (float)y0, wx = fx - (float)x0;
    int z1 = min(z0 + 1, 31), y1 = min(y0 + 1, 255);

    // pair buffer already encodes the x1 = min(x0+1,255) clamp
    int q00 = z0 * 65536 + y0 * 256 + x0;
    int q01 = z0 * 65536 + y1 * 256 + x0;
    int q10 = z1 * 65536 + y0 * 256 + x0;
    int q11 = z1 * 65536 + y1 * 256 + x0;
    int pix = i0 * 65536 + i1 * 256 + i2;

    float iwx = 1.f - wx, iwy = 1.f - wy, iwz = 1.f - wz;

    // ALL 48 gather loads issued before any consumption: MLP=48/warp covers
    // L1/L2 latency; the long-scoreboard wait happens once, not 3x.
    __half2 v[48];
    #pragma unroll
    for (int bc = 0; bc < 12; bc++) {
        const __half2* p = d_pairs + (size_t)bc * PIX;
        v[bc*4+0] = __ldg(p + q00);
        v[bc*4+1] = __ldg(p + q01);
        v[bc*4+2] = __ldg(p + q10);
        v[bc*4+3] = __ldg(p + q11);
    }
    #pragma unroll
    for (int bc = 0; bc < 12; bc++) {
        float2 v00 = __half22float2(v[bc*4+0]);
        float2 v01 = __half22float2(v[bc*4+1]);
        float2 v10 = __half22float2(v[bc*4+2]);
        float2 v11 = __half22float2(v[bc*4+3]);
        float c00 = v00.x * iwx + v00.y * wx;
        float c01 = v01.x * iwx + v01.y * wx;
        float c10 = v10.x * iwx + v10.y * wx;
        float c11 = v11.x * iwx + v11.y * wx;
        float c0 = c00 * iwy + c01 * wy;
        float c1 = c10 * iwy + c11 * wy;
        __stcs(out + (size_t)bc * PIX + pix, c0 * iwz + c1 * wz);
    }
}

extern "C" void kernel_launch(void* const* d_in, const int* in_sizes, int n_in,
                              void* d_out, int out_size) {
    const float* fr       = (const float*)d_in[0];
    const float* seeds    = (const float*)d_in[1];
    const float* Pk       = (const float*)d_in[2];
    const float* defscale = (const float*)d_in[3];
    const int*   feed_idx = (const int*)d_in[5];
    int fdim = in_sizes[5];

    pack_build_kernel<<<PACK_BLOCKS + 1, 256>>>(fr, seeds, Pk, defscale, feed_idx, fdim);
    dim3 g(256, 32);
    deform_kernel<<<g, 256>>>((float*)d_out);
}